// round 9
// baseline (speedup 1.0000x reference)
#include <cuda_runtime.h>
#include <math.h>

#define BATCH  128
#define NNODE  512
#define NN     (BATCH*NNODE)   // 65536
#define F_IN   75
#define H_DIM  128
#define T_OUT  12
#define MAXD   10
#define NDEG   11

#define BM 128
#define BN 128
#define BK 16
#define GX ((NN + BM - 1)/BM)   // 512

#define NSTAT_BLK 512

typedef unsigned long long u64;

__device__ __forceinline__ u64 pack2(float lo, float hi) {
    u64 r; asm("mov.b64 %0, {%1,%2};" : "=l"(r) : "f"(lo), "f"(hi)); return r;
}
__device__ __forceinline__ void fma2(u64& d, u64 a, u64 b) {
    asm("fma.rn.f32x2 %0, %1, %2, %0;" : "+l"(d) : "l"(a), "l"(b));
}
__device__ __forceinline__ void unpack2(float& lo, float& hi, u64 v) {
    asm("mov.b64 {%0,%1}, %2;" : "=f"(lo), "=f"(hi) : "l"(v));
}

// ------------------- device scratch -------------------
__device__ float g_ns[(size_t)NN * H_DIM];
__device__ float g_h1[(size_t)NN * H_DIM];
__device__ float g_h2[(size_t)NN * H_DIM];
__device__ int   g_bucket[NDEG][NN];
__device__ int   g_cnt[NDEG];
__device__ float g_psum[NSTAT_BLK * H_DIM];
__device__ float g_psq [NSTAT_BLK * H_DIM];
__device__ float g_mu[H_DIM];
__device__ float g_rs[H_DIM];

// ------------------- bucketing -------------------
__global__ void zero_cnt_kernel() {
    if (threadIdx.x < NDEG) g_cnt[threadIdx.x] = 0;
}

__global__ void bucket_kernel(const int* __restrict__ deg) {
    int i = blockIdx.x * blockDim.x + threadIdx.x;
    if (i < NN) {
        int d = deg[i];
        int p = atomicAdd(&g_cnt[d], 1);
        g_bucket[d][p] = i;
    }
}

// ------------------- neighbor sums -------------------
__global__ void nsum1_kernel(const float* __restrict__ x,
                             const int* __restrict__ adj,
                             const int* __restrict__ deg) {
    int gw   = (blockIdx.x * blockDim.x + threadIdx.x) >> 5;
    int lane = threadIdx.x & 31;
    if (gw >= NN) return;
    int b = gw / NNODE;
    int d = deg[gw];
    const int* a = adj + (size_t)gw * MAXD;
    int av = (lane < MAXD) ? a[lane] : 0;
    float acc0 = 0.f, acc1 = 0.f, acc2 = 0.f;
    int base = b * NNODE;
    for (int k = 0; k < d; k++) {
        int nb = __shfl_sync(0xffffffffu, av, k);
        const float* row = x + (size_t)(base + nb) * F_IN;
        acc0 += row[lane];
        acc1 += row[lane + 32];
        if (lane < F_IN - 64) acc2 += row[lane + 64];
    }
    float* o = g_ns + (size_t)gw * F_IN;
    o[lane]      = acc0;
    o[lane + 32] = acc1;
    if (lane < F_IN - 64) o[lane + 64] = acc2;
}

__global__ void nsum2_kernel(const int* __restrict__ adj,
                             const int* __restrict__ deg) {
    int gw   = (blockIdx.x * blockDim.x + threadIdx.x) >> 5;
    int lane = threadIdx.x & 31;
    if (gw >= NN) return;
    int b = gw >> 9;
    int d = deg[gw];
    const int* a = adj + (size_t)gw * MAXD;
    int av = (lane < MAXD) ? a[lane] : 0;
    float4 acc = make_float4(0.f, 0.f, 0.f, 0.f);
    int base = b << 9;
    for (int k = 0; k < d; k++) {
        int nb = __shfl_sync(0xffffffffu, av, k);
        const float4* row = (const float4*)(g_h1 + ((size_t)(base + nb) << 7));
        float4 v = row[lane];
        acc.x += v.x; acc.y += v.y; acc.z += v.z; acc.w += v.w;
    }
    ((float4*)(g_ns + ((size_t)gw << 7)))[lane] = acc;
}

// ------------------- degree-grouped GEMM (128x128x16, 8x8/thread, FFMA2) ---
template<int KIN, int LAYER>
__global__ void __launch_bounds__(256, 2)
gconv_gemm(const float* __restrict__ xin,
           const float* __restrict__ Wself,   // [NDEG, KIN, H]
           const float* __restrict__ Wneigh,  // [MAXD, KIN, H]
           const float* __restrict__ bself,   // [NDEG, H]
           const float* __restrict__ bneigh)  // [MAXD, H]
{
    const int d   = blockIdx.y;
    const int cnt = g_cnt[d];
    const int m0  = blockIdx.x * BM;
    if (m0 >= cnt) return;

    const float* hsrc = (LAYER == 1) ? xin : g_h1;
    float* outp       = (LAYER == 1) ? g_h1 : g_h2;

    const float* Ws = Wself + (size_t)d * KIN * H_DIM;
    const float* Wn = Wneigh + (size_t)(d > 0 ? d - 1 : 0) * KIN * H_DIM;
    const int Ktot  = (d > 0) ? 2 * KIN : KIN;
    const int nT    = (Ktot + BK - 1) / BK;

    __shared__ int nodes[BM];
    __shared__ __align__(16) float As[2][BK][BM];
    __shared__ __align__(16) float Bs[2][BK][BN];

    const int tid = threadIdx.x;
    if (tid < BM) nodes[tid] = (m0 + tid < cnt) ? g_bucket[d][m0 + tid] : -1;
    __syncthreads();

    // loader thread mapping
    const int lm   = tid >> 1;            // A row 0..127
    const int lkk0 = (tid & 1) * 8;       // A k-subchunk 0 or 8
    const int lnode = nodes[lm];
    const float* srcA = hsrc + (size_t)(lnode < 0 ? 0 : lnode) * KIN;
    const float* srcN = g_ns + (size_t)(lnode < 0 ? 0 : lnode) * KIN;
    const int bkk = tid >> 4;             // B kk 0..15
    const int bn0 = (tid & 15) * 8;       // B col chunk

    auto load_tile = [&](int s, int t) {
        const int k0 = t * BK;
        // ---- A tile (gathered) ----
        if constexpr (KIN % 8 == 0) {
            int k = k0 + lkk0;
            float4 u0, u1;
            if (lnode >= 0) {
                const float* p = (k < KIN) ? (srcA + k) : (srcN + (k - KIN));
                u0 = *(const float4*)p;
                u1 = *(const float4*)(p + 4);
            } else {
                u0 = make_float4(0.f,0.f,0.f,0.f);
                u1 = u0;
            }
            As[s][lkk0 + 0][lm] = u0.x; As[s][lkk0 + 1][lm] = u0.y;
            As[s][lkk0 + 2][lm] = u0.z; As[s][lkk0 + 3][lm] = u0.w;
            As[s][lkk0 + 4][lm] = u1.x; As[s][lkk0 + 5][lm] = u1.y;
            As[s][lkk0 + 6][lm] = u1.z; As[s][lkk0 + 7][lm] = u1.w;
        } else {
            #pragma unroll
            for (int j = 0; j < 8; j++) {
                int k = k0 + lkk0 + j;
                float v = 0.f;
                if (lnode >= 0 && k < Ktot)
                    v = (k < KIN) ? srcA[k] : srcN[k - KIN];
                As[s][lkk0 + j][lm] = v;
            }
        }
        // ---- B tile ----
        {
            int k = k0 + bkk;
            float4 b0, b1;
            if (k < Ktot) {
                const float* p = (k < KIN) ? (Ws + (size_t)k * H_DIM + bn0)
                                           : (Wn + (size_t)(k - KIN) * H_DIM + bn0);
                b0 = *(const float4*)p;
                b1 = *(const float4*)(p + 4);
            } else {
                b0 = make_float4(0.f,0.f,0.f,0.f);
                b1 = b0;
            }
            *(float4*)&Bs[s][bkk][bn0]     = b0;
            *(float4*)&Bs[s][bkk][bn0 + 4] = b1;
        }
    };

    const int tr = tid >> 4;   // 0..15 -> rows tr*8..+7
    const int tc = tid & 15;   // 0..15 -> cols tc*8..+7

    // acc2[i2][j]: f32x2 lanes = rows (tr*8+2*i2, tr*8+2*i2+1), column tc*8+j
    u64 acc2[4][8];
    #pragma unroll
    for (int i = 0; i < 4; i++)
        #pragma unroll
        for (int j = 0; j < 8; j++) acc2[i][j] = 0ull;

    load_tile(0, 0);
    __syncthreads();

    for (int t = 0; t < nT; t++) {
        const int cur = t & 1;
        if (t + 1 < nT) load_tile(cur ^ 1, t + 1);

        #pragma unroll
        for (int kk = 0; kk < BK; kk++) {
            float4 a0 = *(const float4*)&As[cur][kk][tr * 8];
            float4 a1 = *(const float4*)&As[cur][kk][tr * 8 + 4];
            float4 b0 = *(const float4*)&Bs[cur][kk][tc * 8];
            float4 b1 = *(const float4*)&Bs[cur][kk][tc * 8 + 4];
            // A row-pairs: free reinterpret of float4 as 2x b64
            u64 ap[4];
            ap[0] = ((const u64*)&a0)[0];  // rows +0,+1
            ap[1] = ((const u64*)&a0)[1];  // rows +2,+3
            ap[2] = ((const u64*)&a1)[0];  // rows +4,+5
            ap[3] = ((const u64*)&a1)[1];  // rows +6,+7
            // B duplicated into both lanes
            u64 bd[8];
            bd[0] = pack2(b0.x, b0.x); bd[1] = pack2(b0.y, b0.y);
            bd[2] = pack2(b0.z, b0.z); bd[3] = pack2(b0.w, b0.w);
            bd[4] = pack2(b1.x, b1.x); bd[5] = pack2(b1.y, b1.y);
            bd[6] = pack2(b1.z, b1.z); bd[7] = pack2(b1.w, b1.w);
            #pragma unroll
            for (int i = 0; i < 4; i++)
                #pragma unroll
                for (int j = 0; j < 8; j++)
                    fma2(acc2[i][j], ap[i], bd[j]);
        }
        __syncthreads();
    }

    // epilogue: bias + scattered store
    float bias[8];
    #pragma unroll
    for (int j = 0; j < 8; j++) {
        int n = tc * 8 + j;
        float bb = bself[(size_t)d * H_DIM + n];
        if (d > 0) bb += bneigh[(size_t)(d - 1) * H_DIM + n];
        bias[j] = bb;
    }
    #pragma unroll
    for (int i2 = 0; i2 < 4; i2++) {
        float r0[8], r1[8];
        #pragma unroll
        for (int j = 0; j < 8; j++) unpack2(r0[j], r1[j], acc2[i2][j]);

        int node0 = nodes[tr * 8 + 2 * i2];
        if (node0 >= 0) {
            float* o = outp + (size_t)node0 * H_DIM + tc * 8;
            float4 v0 = make_float4(r0[0] + bias[0], r0[1] + bias[1],
                                    r0[2] + bias[2], r0[3] + bias[3]);
            float4 v1 = make_float4(r0[4] + bias[4], r0[5] + bias[5],
                                    r0[6] + bias[6], r0[7] + bias[7]);
            *(float4*)(o)     = v0;
            *(float4*)(o + 4) = v1;
        }
        int node1 = nodes[tr * 8 + 2 * i2 + 1];
        if (node1 >= 0) {
            float* o = outp + (size_t)node1 * H_DIM + tc * 8;
            float4 v0 = make_float4(r1[0] + bias[0], r1[1] + bias[1],
                                    r1[2] + bias[2], r1[3] + bias[3]);
            float4 v1 = make_float4(r1[4] + bias[4], r1[5] + bias[5],
                                    r1[6] + bias[6], r1[7] + bias[7]);
            *(float4*)(o)     = v0;
            *(float4*)(o + 4) = v1;
        }
    }
}

// ------------------- batch norm (deterministic two-pass) -------------------
template<int LAYER>
__global__ void bn_stats_kernel() {
    const float* h = (LAYER == 1) ? g_h1 : g_h2;
    int c = threadIdx.x;                     // 128 threads
    int r0 = blockIdx.x * (NN / NSTAT_BLK);  // 128 rows per block
    float s = 0.f, s2 = 0.f;
    const float* p = h + (size_t)r0 * H_DIM + c;
    #pragma unroll 8
    for (int r = 0; r < NN / NSTAT_BLK; r++) {
        float v = p[(size_t)r * H_DIM];
        s += v; s2 += v * v;
    }
    g_psum[blockIdx.x * H_DIM + c] = s;
    g_psq [blockIdx.x * H_DIM + c] = s2;
}

__global__ void bn_finalize_kernel() {
    int g = threadIdx.x >> 7;
    int c = threadIdx.x & 127;
    float s = 0.f, s2 = 0.f;
    #pragma unroll 8
    for (int i = g; i < NSTAT_BLK; i += 4) {
        s  += g_psum[i * H_DIM + c];
        s2 += g_psq [i * H_DIM + c];
    }
    __shared__ float ss[4][H_DIM], ss2[4][H_DIM];
    ss[g][c] = s; ss2[g][c] = s2;
    __syncthreads();
    if (g == 0) {
        s  = ss[0][c]  + ss[1][c]  + ss[2][c]  + ss[3][c];
        s2 = ss2[0][c] + ss2[1][c] + ss2[2][c] + ss2[3][c];
        float mu  = s / (float)NN;
        float var = s2 / (float)NN - mu * mu;
        g_mu[c] = mu;
        g_rs[c] = rsqrtf(var + 1e-5f);
    }
}

template<int LAYER>
__global__ void bn_relu_kernel(const float* __restrict__ gamma,
                               const float* __restrict__ beta) {
    float* h = (LAYER == 1) ? g_h1 : g_h2;
    size_t i = (size_t)blockIdx.x * blockDim.x + threadIdx.x;
    if (i >= (size_t)NN * (H_DIM / 4)) return;
    int c = ((int)(i & (H_DIM / 4 - 1))) * 4;
    float4 v = ((float4*)h)[i];
    v.x = fmaxf(0.f, (v.x - g_mu[c + 0]) * g_rs[c + 0] * gamma[c + 0] + beta[c + 0]);
    v.y = fmaxf(0.f, (v.y - g_mu[c + 1]) * g_rs[c + 1] * gamma[c + 1] + beta[c + 1]);
    v.z = fmaxf(0.f, (v.z - g_mu[c + 2]) * g_rs[c + 2] * gamma[c + 2] + beta[c + 2]);
    v.w = fmaxf(0.f, (v.w - g_mu[c + 3]) * g_rs[c + 3] * gamma[c + 3] + beta[c + 3]);
    ((float4*)h)[i] = v;
}

// ------------------- mean pool + dense (512 threads, uniform syncs) --------
__global__ void pool_dense_kernel(const float* __restrict__ Wd,
                                  const float* __restrict__ bd,
                                  float* __restrict__ out) {
    int b = blockIdx.x;            // 128
    int g = threadIdx.x >> 7;      // 0..3
    int c = threadIdx.x & 127;     // column
    float s = 0.f;
    const float* p = g_h2 + (size_t)b * NNODE * H_DIM + c;
    #pragma unroll 8
    for (int n = g; n < NNODE; n += 4) s += p[(size_t)n * H_DIM];
    __shared__ float part[4][H_DIM];
    __shared__ float pv[H_DIM];
    part[g][c] = s;
    __syncthreads();
    if (g == 0)
        pv[c] = (part[0][c] + part[1][c] + part[2][c] + part[3][c]) * (1.0f / NNODE);
    __syncthreads();
    if (threadIdx.x < T_OUT) {
        float o = bd[c];
        #pragma unroll 8
        for (int j = 0; j < H_DIM; j++) o += pv[j] * Wd[j * T_OUT + c];
        out[b * T_OUT + c] = o;
    }
}

// ------------------- launch -------------------
extern "C" void kernel_launch(void* const* d_in, const int* in_sizes, int n_in,
                              void* d_out, int out_size) {
    const float* x      = (const float*)d_in[0];
    const int*   adj    = (const int*)  d_in[1];
    const int*   deg    = (const int*)  d_in[2];
    const float* Wn1    = (const float*)d_in[3];
    const float* Ws1    = (const float*)d_in[4];
    const float* bn1    = (const float*)d_in[5];
    const float* bs1    = (const float*)d_in[6];
    const float* gamma1 = (const float*)d_in[7];
    const float* beta1  = (const float*)d_in[8];
    const float* Wn2    = (const float*)d_in[9];
    const float* Ws2    = (const float*)d_in[10];
    const float* bn2    = (const float*)d_in[11];
    const float* bs2    = (const float*)d_in[12];
    const float* gamma2 = (const float*)d_in[13];
    const float* beta2  = (const float*)d_in[14];
    const float* Wd     = (const float*)d_in[15];
    const float* bd     = (const float*)d_in[16];
    float* out = (float*)d_out;

    zero_cnt_kernel<<<1, 32>>>();
    bucket_kernel<<<NN / 256, 256>>>(deg);

    // ---- layer 1 ----
    nsum1_kernel<<<NN / 8, 256>>>(x, adj, deg);
    {
        dim3 grid(GX, NDEG);
        gconv_gemm<F_IN, 1><<<grid, 256>>>(x, Ws1, Wn1, bs1, bn1);
    }
    bn_stats_kernel<1><<<NSTAT_BLK, H_DIM>>>();
    bn_finalize_kernel<<<1, 512>>>();
    bn_relu_kernel<1><<<(NN * (H_DIM / 4)) / 256, 256>>>(gamma1, beta1);

    // ---- layer 2 ----
    nsum2_kernel<<<NN / 8, 256>>>(adj, deg);
    {
        dim3 grid(GX, NDEG);
        gconv_gemm<H_DIM, 2><<<grid, 256>>>(x /*unused*/, Ws2, Wn2, bs2, bn2);
    }
    bn_stats_kernel<2><<<NSTAT_BLK, H_DIM>>>();
    bn_finalize_kernel<<<1, 512>>>();
    bn_relu_kernel<2><<<(NN * (H_DIM / 4)) / 256, 256>>>(gamma2, beta2);

    // ---- pool + dense ----
    pool_dense_kernel<<<BATCH, 512>>>(Wd, bd, out);
}

// round 10
// speedup vs baseline: 1.0012x; 1.0012x over previous
#include <cuda_runtime.h>
#include <math.h>

#define BATCH  128
#define NNODE  512
#define NN     (BATCH*NNODE)   // 65536
#define F_IN   75
#define H_DIM  128
#define T_OUT  12
#define MAXD   10
#define NDEG   11

#define BM 128
#define BN 128
#define BK 16
#define GX ((NN + BM - 1)/BM)   // 512

#define NSTAT_BLK 512

typedef unsigned long long u64;

__device__ __forceinline__ u64 pack2(float lo, float hi) {
    u64 r; asm("mov.b64 %0, {%1,%2};" : "=l"(r) : "f"(lo), "f"(hi)); return r;
}
__device__ __forceinline__ void fma2(u64& d, u64 a, u64 b) {
    asm("fma.rn.f32x2 %0, %1, %2, %0;" : "+l"(d) : "l"(a), "l"(b));
}
__device__ __forceinline__ void unpack2(float& lo, float& hi, u64 v) {
    asm("mov.b64 {%0,%1}, %2;" : "=f"(lo), "=f"(hi) : "l"(v));
}

// ------------------- device scratch -------------------
__device__ float g_ns[(size_t)NN * H_DIM];
__device__ float g_h1[(size_t)NN * H_DIM];
__device__ float g_h2[(size_t)NN * H_DIM];
__device__ int   g_bucket[NDEG][NN];
__device__ int   g_cnt[NDEG];
__device__ float g_psum[NSTAT_BLK * H_DIM];
__device__ float g_psq [NSTAT_BLK * H_DIM];
__device__ float g_mu[H_DIM];
__device__ float g_rs[H_DIM];

// ------------------- bucketing -------------------
__global__ void zero_cnt_kernel() {
    if (threadIdx.x < NDEG) g_cnt[threadIdx.x] = 0;
}

__global__ void bucket_kernel(const int* __restrict__ deg) {
    int i = blockIdx.x * blockDim.x + threadIdx.x;
    if (i < NN) {
        int d = deg[i];
        int p = atomicAdd(&g_cnt[d], 1);
        g_bucket[d][p] = i;
    }
}

// ------------------- neighbor sums -------------------
__global__ void nsum1_kernel(const float* __restrict__ x,
                             const int* __restrict__ adj,
                             const int* __restrict__ deg) {
    int gw   = (blockIdx.x * blockDim.x + threadIdx.x) >> 5;
    int lane = threadIdx.x & 31;
    if (gw >= NN) return;
    int b = gw / NNODE;
    int d = deg[gw];
    const int* a = adj + (size_t)gw * MAXD;
    int av = (lane < MAXD) ? a[lane] : 0;
    float acc0 = 0.f, acc1 = 0.f, acc2 = 0.f;
    int base = b * NNODE;
    for (int k = 0; k < d; k++) {
        int nb = __shfl_sync(0xffffffffu, av, k);
        const float* row = x + (size_t)(base + nb) * F_IN;
        acc0 += row[lane];
        acc1 += row[lane + 32];
        if (lane < F_IN - 64) acc2 += row[lane + 64];
    }
    float* o = g_ns + (size_t)gw * F_IN;
    o[lane]      = acc0;
    o[lane + 32] = acc1;
    if (lane < F_IN - 64) o[lane + 64] = acc2;
}

__global__ void nsum2_kernel(const int* __restrict__ adj,
                             const int* __restrict__ deg) {
    int gw   = (blockIdx.x * blockDim.x + threadIdx.x) >> 5;
    int lane = threadIdx.x & 31;
    if (gw >= NN) return;
    int b = gw >> 9;
    int d = deg[gw];
    const int* a = adj + (size_t)gw * MAXD;
    int av = (lane < MAXD) ? a[lane] : 0;
    float4 acc = make_float4(0.f, 0.f, 0.f, 0.f);
    int base = b << 9;
    for (int k = 0; k < d; k++) {
        int nb = __shfl_sync(0xffffffffu, av, k);
        const float4* row = (const float4*)(g_h1 + ((size_t)(base + nb) << 7));
        float4 v = row[lane];
        acc.x += v.x; acc.y += v.y; acc.z += v.z; acc.w += v.w;
    }
    ((float4*)(g_ns + ((size_t)gw << 7)))[lane] = acc;
}

// ------------------- degree-grouped GEMM (128x128x16, 8x8/thread, FFMA2) ---
template<int KIN, int LAYER>
__global__ void __launch_bounds__(256, 2)
gconv_gemm(const float* __restrict__ xin,
           const float* __restrict__ Wself,   // [NDEG, KIN, H]
           const float* __restrict__ Wneigh,  // [MAXD, KIN, H]
           const float* __restrict__ bself,   // [NDEG, H]
           const float* __restrict__ bneigh)  // [MAXD, H]
{
    const int d   = blockIdx.y;
    const int cnt = g_cnt[d];
    const int m0  = blockIdx.x * BM;
    if (m0 >= cnt) return;

    const float* hsrc = (LAYER == 1) ? xin : g_h1;
    float* outp       = (LAYER == 1) ? g_h1 : g_h2;

    const float* Ws = Wself + (size_t)d * KIN * H_DIM;
    const float* Wn = Wneigh + (size_t)(d > 0 ? d - 1 : 0) * KIN * H_DIM;
    const int Ktot  = (d > 0) ? 2 * KIN : KIN;
    const int nT    = (Ktot + BK - 1) / BK;

    __shared__ int nodes[BM];
    __shared__ __align__(16) float As[2][BK][BM];
    __shared__ __align__(16) float Bs[2][BK][BN];

    const int tid = threadIdx.x;
    if (tid < BM) nodes[tid] = (m0 + tid < cnt) ? g_bucket[d][m0 + tid] : -1;
    __syncthreads();

    // loader thread mapping
    const int lm   = tid >> 1;            // A row 0..127
    const int lkk0 = (tid & 1) * 8;       // A k-subchunk 0 or 8
    const int lnode = nodes[lm];
    const float* srcA = hsrc + (size_t)(lnode < 0 ? 0 : lnode) * KIN;
    const float* srcN = g_ns + (size_t)(lnode < 0 ? 0 : lnode) * KIN;
    const int bkk = tid >> 4;             // B kk 0..15
    const int bn0 = (tid & 15) * 8;       // B col chunk

    auto load_tile = [&](int s, int t) {
        const int k0 = t * BK;
        // ---- A tile (gathered) ----
        if constexpr (KIN % 8 == 0) {
            int k = k0 + lkk0;
            float4 u0, u1;
            if (lnode >= 0) {
                const float* p = (k < KIN) ? (srcA + k) : (srcN + (k - KIN));
                u0 = *(const float4*)p;
                u1 = *(const float4*)(p + 4);
            } else {
                u0 = make_float4(0.f,0.f,0.f,0.f);
                u1 = u0;
            }
            As[s][lkk0 + 0][lm] = u0.x; As[s][lkk0 + 1][lm] = u0.y;
            As[s][lkk0 + 2][lm] = u0.z; As[s][lkk0 + 3][lm] = u0.w;
            As[s][lkk0 + 4][lm] = u1.x; As[s][lkk0 + 5][lm] = u1.y;
            As[s][lkk0 + 6][lm] = u1.z; As[s][lkk0 + 7][lm] = u1.w;
        } else {
            #pragma unroll
            for (int j = 0; j < 8; j++) {
                int k = k0 + lkk0 + j;
                float v = 0.f;
                if (lnode >= 0 && k < Ktot)
                    v = (k < KIN) ? srcA[k] : srcN[k - KIN];
                As[s][lkk0 + j][lm] = v;
            }
        }
        // ---- B tile ----
        {
            int k = k0 + bkk;
            float4 b0, b1;
            if (k < Ktot) {
                const float* p = (k < KIN) ? (Ws + (size_t)k * H_DIM + bn0)
                                           : (Wn + (size_t)(k - KIN) * H_DIM + bn0);
                b0 = *(const float4*)p;
                b1 = *(const float4*)(p + 4);
            } else {
                b0 = make_float4(0.f,0.f,0.f,0.f);
                b1 = b0;
            }
            *(float4*)&Bs[s][bkk][bn0]     = b0;
            *(float4*)&Bs[s][bkk][bn0 + 4] = b1;
        }
    };

    const int tr = tid >> 4;   // 0..15 -> rows tr*8..+7
    const int tc = tid & 15;   // 0..15 -> cols tc*8..+7

    // acc2[i2][j]: f32x2 lanes = rows (tr*8+2*i2, tr*8+2*i2+1), column tc*8+j
    u64 acc2[4][8];
    #pragma unroll
    for (int i = 0; i < 4; i++)
        #pragma unroll
        for (int j = 0; j < 8; j++) acc2[i][j] = 0ull;

    load_tile(0, 0);
    __syncthreads();

    for (int t = 0; t < nT; t++) {
        const int cur = t & 1;
        if (t + 1 < nT) load_tile(cur ^ 1, t + 1);

        #pragma unroll
        for (int kk = 0; kk < BK; kk++) {
            float4 a0 = *(const float4*)&As[cur][kk][tr * 8];
            float4 a1 = *(const float4*)&As[cur][kk][tr * 8 + 4];
            float4 b0 = *(const float4*)&Bs[cur][kk][tc * 8];
            float4 b1 = *(const float4*)&Bs[cur][kk][tc * 8 + 4];
            // A row-pairs: free reinterpret of float4 as 2x b64
            u64 ap[4];
            ap[0] = ((const u64*)&a0)[0];  // rows +0,+1
            ap[1] = ((const u64*)&a0)[1];  // rows +2,+3
            ap[2] = ((const u64*)&a1)[0];  // rows +4,+5
            ap[3] = ((const u64*)&a1)[1];  // rows +6,+7
            // B duplicated into both lanes
            u64 bd[8];
            bd[0] = pack2(b0.x, b0.x); bd[1] = pack2(b0.y, b0.y);
            bd[2] = pack2(b0.z, b0.z); bd[3] = pack2(b0.w, b0.w);
            bd[4] = pack2(b1.x, b1.x); bd[5] = pack2(b1.y, b1.y);
            bd[6] = pack2(b1.z, b1.z); bd[7] = pack2(b1.w, b1.w);
            #pragma unroll
            for (int i = 0; i < 4; i++)
                #pragma unroll
                for (int j = 0; j < 8; j++)
                    fma2(acc2[i][j], ap[i], bd[j]);
        }
        __syncthreads();
    }

    // epilogue: bias + scattered store
    float bias[8];
    #pragma unroll
    for (int j = 0; j < 8; j++) {
        int n = tc * 8 + j;
        float bb = bself[(size_t)d * H_DIM + n];
        if (d > 0) bb += bneigh[(size_t)(d - 1) * H_DIM + n];
        bias[j] = bb;
    }
    #pragma unroll
    for (int i2 = 0; i2 < 4; i2++) {
        float r0[8], r1[8];
        #pragma unroll
        for (int j = 0; j < 8; j++) unpack2(r0[j], r1[j], acc2[i2][j]);

        int node0 = nodes[tr * 8 + 2 * i2];
        if (node0 >= 0) {
            float* o = outp + (size_t)node0 * H_DIM + tc * 8;
            float4 v0 = make_float4(r0[0] + bias[0], r0[1] + bias[1],
                                    r0[2] + bias[2], r0[3] + bias[3]);
            float4 v1 = make_float4(r0[4] + bias[4], r0[5] + bias[5],
                                    r0[6] + bias[6], r0[7] + bias[7]);
            *(float4*)(o)     = v0;
            *(float4*)(o + 4) = v1;
        }
        int node1 = nodes[tr * 8 + 2 * i2 + 1];
        if (node1 >= 0) {
            float* o = outp + (size_t)node1 * H_DIM + tc * 8;
            float4 v0 = make_float4(r1[0] + bias[0], r1[1] + bias[1],
                                    r1[2] + bias[2], r1[3] + bias[3]);
            float4 v1 = make_float4(r1[4] + bias[4], r1[5] + bias[5],
                                    r1[6] + bias[6], r1[7] + bias[7]);
            *(float4*)(o)     = v0;
            *(float4*)(o + 4) = v1;
        }
    }
}

// ------------------- batch norm (deterministic two-pass) -------------------
template<int LAYER>
__global__ void bn_stats_kernel() {
    const float* h = (LAYER == 1) ? g_h1 : g_h2;
    int c = threadIdx.x;                     // 128 threads
    int r0 = blockIdx.x * (NN / NSTAT_BLK);  // 128 rows per block
    float s = 0.f, s2 = 0.f;
    const float* p = h + (size_t)r0 * H_DIM + c;
    #pragma unroll 8
    for (int r = 0; r < NN / NSTAT_BLK; r++) {
        float v = p[(size_t)r * H_DIM];
        s += v; s2 += v * v;
    }
    g_psum[blockIdx.x * H_DIM + c] = s;
    g_psq [blockIdx.x * H_DIM + c] = s2;
}

__global__ void bn_finalize_kernel() {
    int g = threadIdx.x >> 7;
    int c = threadIdx.x & 127;
    float s = 0.f, s2 = 0.f;
    #pragma unroll 8
    for (int i = g; i < NSTAT_BLK; i += 4) {
        s  += g_psum[i * H_DIM + c];
        s2 += g_psq [i * H_DIM + c];
    }
    __shared__ float ss[4][H_DIM], ss2[4][H_DIM];
    ss[g][c] = s; ss2[g][c] = s2;
    __syncthreads();
    if (g == 0) {
        s  = ss[0][c]  + ss[1][c]  + ss[2][c]  + ss[3][c];
        s2 = ss2[0][c] + ss2[1][c] + ss2[2][c] + ss2[3][c];
        float mu  = s / (float)NN;
        float var = s2 / (float)NN - mu * mu;
        g_mu[c] = mu;
        g_rs[c] = rsqrtf(var + 1e-5f);
    }
}

template<int LAYER>
__global__ void bn_relu_kernel(const float* __restrict__ gamma,
                               const float* __restrict__ beta) {
    float* h = (LAYER == 1) ? g_h1 : g_h2;
    size_t i = (size_t)blockIdx.x * blockDim.x + threadIdx.x;
    if (i >= (size_t)NN * (H_DIM / 4)) return;
    int c = ((int)(i & (H_DIM / 4 - 1))) * 4;
    float4 v = ((float4*)h)[i];
    v.x = fmaxf(0.f, (v.x - g_mu[c + 0]) * g_rs[c + 0] * gamma[c + 0] + beta[c + 0]);
    v.y = fmaxf(0.f, (v.y - g_mu[c + 1]) * g_rs[c + 1] * gamma[c + 1] + beta[c + 1]);
    v.z = fmaxf(0.f, (v.z - g_mu[c + 2]) * g_rs[c + 2] * gamma[c + 2] + beta[c + 2]);
    v.w = fmaxf(0.f, (v.w - g_mu[c + 3]) * g_rs[c + 3] * gamma[c + 3] + beta[c + 3]);
    ((float4*)h)[i] = v;
}

// ------------------- mean pool + dense (512 threads, uniform syncs) --------
__global__ void pool_dense_kernel(const float* __restrict__ Wd,
                                  const float* __restrict__ bd,
                                  float* __restrict__ out) {
    int b = blockIdx.x;            // 128
    int g = threadIdx.x >> 7;      // 0..3
    int c = threadIdx.x & 127;     // column
    float s = 0.f;
    const float* p = g_h2 + (size_t)b * NNODE * H_DIM + c;
    #pragma unroll 8
    for (int n = g; n < NNODE; n += 4) s += p[(size_t)n * H_DIM];
    __shared__ float part[4][H_DIM];
    __shared__ float pv[H_DIM];
    part[g][c] = s;
    __syncthreads();
    if (g == 0)
        pv[c] = (part[0][c] + part[1][c] + part[2][c] + part[3][c]) * (1.0f / NNODE);
    __syncthreads();
    if (threadIdx.x < T_OUT) {
        float o = bd[c];
        #pragma unroll 8
        for (int j = 0; j < H_DIM; j++) o += pv[j] * Wd[j * T_OUT + c];
        out[b * T_OUT + c] = o;
    }
}

// ------------------- launch -------------------
extern "C" void kernel_launch(void* const* d_in, const int* in_sizes, int n_in,
                              void* d_out, int out_size) {
    const float* x      = (const float*)d_in[0];
    const int*   adj    = (const int*)  d_in[1];
    const int*   deg    = (const int*)  d_in[2];
    const float* Wn1    = (const float*)d_in[3];
    const float* Ws1    = (const float*)d_in[4];
    const float* bn1    = (const float*)d_in[5];
    const float* bs1    = (const float*)d_in[6];
    const float* gamma1 = (const float*)d_in[7];
    const float* beta1  = (const float*)d_in[8];
    const float* Wn2    = (const float*)d_in[9];
    const float* Ws2    = (const float*)d_in[10];
    const float* bn2    = (const float*)d_in[11];
    const float* bs2    = (const float*)d_in[12];
    const float* gamma2 = (const float*)d_in[13];
    const float* beta2  = (const float*)d_in[14];
    const float* Wd     = (const float*)d_in[15];
    const float* bd     = (const float*)d_in[16];
    float* out = (float*)d_out;

    zero_cnt_kernel<<<1, 32>>>();
    bucket_kernel<<<NN / 256, 256>>>(deg);

    // ---- layer 1 ----
    nsum1_kernel<<<NN / 8, 256>>>(x, adj, deg);
    {
        dim3 grid(GX, NDEG);
        gconv_gemm<F_IN, 1><<<grid, 256>>>(x, Ws1, Wn1, bs1, bn1);
    }
    bn_stats_kernel<1><<<NSTAT_BLK, H_DIM>>>();
    bn_finalize_kernel<<<1, 512>>>();
    bn_relu_kernel<1><<<(NN * (H_DIM / 4)) / 256, 256>>>(gamma1, beta1);

    // ---- layer 2 ----
    nsum2_kernel<<<NN / 8, 256>>>(adj, deg);
    {
        dim3 grid(GX, NDEG);
        gconv_gemm<H_DIM, 2><<<grid, 256>>>(x /*unused*/, Ws2, Wn2, bs2, bn2);
    }
    bn_stats_kernel<2><<<NSTAT_BLK, H_DIM>>>();
    bn_finalize_kernel<<<1, 512>>>();
    bn_relu_kernel<2><<<(NN * (H_DIM / 4)) / 256, 256>>>(gamma2, beta2);

    // ---- pool + dense ----
    pool_dense_kernel<<<BATCH, 512>>>(Wd, bd, out);
}